// round 17
// baseline (speedup 1.0000x reference)
#include <cuda_runtime.h>
#include <math.h>
#include <stdint.h>

// LongcatFlashTopkRouter: T=16384, D=4096, E=256
#define TOP_K 8
#define ROUTED_SCALE 1.5f

#if defined(__CUDA_ARCH__) && \
    (defined(__CUDA_ARCH_FEAT_SM103_ALL) || defined(__CUDA_ARCH_FEAT_SM100_ALL) || \
     defined(__CUDA_ARCH_FEAT_SM101_ALL))
#define HAS_TC 1
#else
#define HAS_TC 0
#endif

// ---------------------------------------------------------------------------
// GEMM: C[t,e] = dot(H[t,:], W[e,:]) via bf16x3 emulation on tcgen05.
// R9/R16 champion core: 4 accumulator chains, NSTAGE=3. R17 adds PDL trigger.
// ---------------------------------------------------------------------------
#define BM 128
#define BN 256
#define BKF 32
#define STAGE_BYTES 49152
#define A_HI_OFF 0
#define A_LO_OFF 8192
#define B_HI_OFF 16384
#define B_LO_OFF 32768
#define NSTAGE 3
#define DYN_SMEM (NSTAGE * STAGE_BYTES + 1024)

// idesc kind::f16 bf16: F32(1)<<4 | BF16(1)<<7 | BF16(1)<<10 | (N=128/8)<<17 | (M=128/16)<<24
#define IDESC 0x8200490u
#define TMEM_NCOLS 512
// D accumulators: D(h, ks) at col h*128 + ks*256

#if HAS_TC
__device__ __forceinline__ uint32_t smem_u32(const void* p) {
    uint32_t a;
    asm("{ .reg .u64 t; cvta.to.shared.u64 t, %1; cvt.u32.u64 %0, t; }" : "=r"(a) : "l"(p));
    return a;
}

// d = { upper = bf16(hi), lower = bf16(lo) }
__device__ __forceinline__ uint32_t pack_bf16x2(float hi, float lo) {
    uint32_t d;
    asm("cvt.rn.bf16x2.f32 %0, %1, %2;" : "=r"(d) : "f"(hi), "f"(lo));
    return d;
}

#define SWZ64(o) ((o) ^ (((o) >> 3) & 0x30))

// SW64 K-major descriptor: layout=4, version=1, SBO=32 (512B/8rows), LBO=1
__device__ __forceinline__ uint64_t mk_desc64(uint32_t addr) {
    const uint64_t base =
        (uint64_t(4) << 61) | (uint64_t(1) << 46) | (uint64_t(32) << 32) | (uint64_t(1) << 16);
    return base | ((uint64_t)(addr >> 4) & 0x3FFF);
}

__device__ __forceinline__ void mma_bf16_ss(uint32_t d_tmem, uint64_t a_desc, uint64_t b_desc,
                                            uint32_t en) {
    uint32_t z = 0;
    asm volatile(
        "{\n\t.reg .pred p;\n\t"
        "setp.ne.u32 p, %5, 0;\n\t"
        "tcgen05.mma.cta_group::1.kind::f16 [%0], %1, %2, %3, {%4, %4, %4, %4}, p;\n\t}"
        :: "r"(d_tmem), "l"(a_desc), "l"(b_desc), "r"(IDESC), "r"(z), "r"(en)
        : "memory");
}

__device__ __forceinline__ void mbar_init(uint32_t mbar, uint32_t cnt) {
    asm volatile("mbarrier.init.shared.b64 [%0], %1;" :: "r"(mbar), "r"(cnt) : "memory");
}

__device__ __forceinline__ void mbar_wait(uint32_t mbar, uint32_t parity) {
    asm volatile(
        "{\n\t.reg .pred P;\n\t"
        "WL_%=:\n\t"
        "mbarrier.try_wait.parity.acquire.cta.shared::cta.b64 P, [%0], %1, 0x989680;\n\t"
        "@P bra.uni WD_%=;\n\t"
        "bra.uni WL_%=;\n\t"
        "WD_%=:\n\t}"
        :: "r"(mbar), "r"(parity) : "memory");
}

#define TC_ALLOC(dst_smem, n) \
    asm volatile("tcgen05.alloc.cta_group::1.sync.aligned.shared::cta.b32 [%0], %1;" \
                 :: "r"(dst_smem), "r"((uint32_t)(n)) : "memory")
#define TC_RELINQ() \
    asm volatile("tcgen05.relinquish_alloc_permit.cta_group::1.sync.aligned;")
#define TC_DEALLOC(tm, n) \
    asm volatile("tcgen05.dealloc.cta_group::1.sync.aligned.b32 %0, %1;" :: "r"(tm), "r"((uint32_t)(n)))
#define TC_COMMIT(mbar) \
    asm volatile("tcgen05.commit.cta_group::1.mbarrier::arrive::one.shared::cluster.b64 [%0];" \
                 :: "r"(mbar) : "memory")
#define TC_FENCE_AFTER()  asm volatile("tcgen05.fence::after_thread_sync;" ::: "memory")
#define TC_FENCE_BEFORE() asm volatile("tcgen05.fence::before_thread_sync;" ::: "memory")
#define FENCE_ASYNC() asm volatile("fence.proxy.async.shared::cta;" ::: "memory")
#define TC_WAIT_LD()  asm volatile("tcgen05.wait::ld.sync.aligned;" ::: "memory")

#define TC_LD_X32(r, addr) \
    asm volatile( \
        "tcgen05.ld.sync.aligned.32x32b.x32.b32 " \
        "{%0, %1, %2, %3, %4, %5, %6, %7, " \
        " %8, %9, %10, %11, %12, %13, %14, %15, " \
        " %16, %17, %18, %19, %20, %21, %22, %23, " \
        " %24, %25, %26, %27, %28, %29, %30, %31}, [%32];" \
        : "=r"((r)[0]),  "=r"((r)[1]),  "=r"((r)[2]),  "=r"((r)[3]), \
          "=r"((r)[4]),  "=r"((r)[5]),  "=r"((r)[6]),  "=r"((r)[7]), \
          "=r"((r)[8]),  "=r"((r)[9]),  "=r"((r)[10]), "=r"((r)[11]), \
          "=r"((r)[12]), "=r"((r)[13]), "=r"((r)[14]), "=r"((r)[15]), \
          "=r"((r)[16]), "=r"((r)[17]), "=r"((r)[18]), "=r"((r)[19]), \
          "=r"((r)[20]), "=r"((r)[21]), "=r"((r)[22]), "=r"((r)[23]), \
          "=r"((r)[24]), "=r"((r)[25]), "=r"((r)[26]), "=r"((r)[27]), \
          "=r"((r)[28]), "=r"((r)[29]), "=r"((r)[30]), "=r"((r)[31]) \
        : "r"(addr))
#endif  // HAS_TC

// warp-wide max: single redux on sm_100a-family, shuffle butterfly otherwise
__device__ __forceinline__ float warp_max_f32(float x) {
#if HAS_TC
    float r;
    asm("redux.sync.max.f32 %0, %1, 0xffffffff;" : "=f"(r) : "f"(x));
    return r;
#else
    #pragma unroll
    for (int off = 16; off > 0; off >>= 1)
        x = fmaxf(x, __shfl_xor_sync(0xffffffffu, x, off));
    return x;
#endif
}

extern __shared__ char g_dyn_smem[];

__global__ __launch_bounds__(256, 1)
void gemm_kernel(const float* __restrict__ A,   // [T, D]
                 const float* __restrict__ W,   // [E, D]
                 float* __restrict__ C,         // [T, E]
                 int D, int E) {
#if HAS_TC
    // ==================== tcgen05 bf16x3, 4 accumulator chains ===============
    __shared__ uint32_t s_tmem;
    __shared__ __align__(16) unsigned long long s_mbar[NSTAGE];

    const int tid  = threadIdx.x;
    const int wid  = tid >> 5;
    const int lane = tid & 31;

    uint32_t raw_u32  = smem_u32(g_dyn_smem);
    uint32_t tile_u32 = (raw_u32 + 1023u) & ~1023u;
    char*    tile_gen = g_dyn_smem + (tile_u32 - raw_u32);

    const uint32_t mbar_u32 = smem_u32(&s_mbar[0]);

    if (wid == 0) TC_ALLOC(smem_u32(&s_tmem), TMEM_NCOLS);
    if (tid == 0) {
        mbar_init(mbar_u32, 1);
        mbar_init(mbar_u32 + 8, 1);
        mbar_init(mbar_u32 + 16, 1);
    }
    __syncthreads();
    const uint32_t tmem = s_tmem;

    const int blockRow = blockIdx.x * BM;

    // producer mapping: group g = tid>>3 (0..31), f4 column tid&7 (0..7)
    const int grp = tid >> 3;
    const int c4  = tid & 7;

    const float* aBase = A + (size_t)(blockRow + grp) * D + c4 * 4;
    const float* bBase = W + (size_t)grp * D + c4 * 4;
    const size_t rstep = (size_t)32 * D;

    const int niter = D / BKF;   // 128
    int ph0 = 0, ph1 = 0, ph2 = 0;
    int s = 0;

    float4 bufA[4], bufB[8];
    #pragma unroll
    for (int q = 0; q < 4; q++) bufA[q] = *(const float4*)(aBase + q * rstep);
    #pragma unroll
    for (int p = 0; p < 8; p++) bufB[p] = *(const float4*)(bBase + p * rstep);

    const uint32_t rowOff = (uint32_t)(grp * 64 + c4 * 8);

    for (int i = 0; i < niter; i++) {
        const uint32_t stage = (uint32_t)s * STAGE_BYTES;

        if (i >= NSTAGE) {
            if      (s == 0) { mbar_wait(mbar_u32,      ph0); ph0 ^= 1; }
            else if (s == 1) { mbar_wait(mbar_u32 + 8,  ph1); ph1 ^= 1; }
            else             { mbar_wait(mbar_u32 + 16, ph2); ph2 ^= 1; }
        }

        // convert fp32 -> (hi, lo) bf16, swizzled STS
        #pragma unroll
        for (int q = 0; q < 4; q++) {
            const uint32_t off = SWZ64(rowOff + (uint32_t)q * 2048);
            float4 f = bufA[q];
            uint32_t h0 = pack_bf16x2(f.y, f.x);
            uint32_t h1 = pack_bf16x2(f.w, f.z);
            float a0 = __uint_as_float(h0 << 16);
            float a1 = __uint_as_float(h0 & 0xFFFF0000u);
            float a2 = __uint_as_float(h1 << 16);
            float a3 = __uint_as_float(h1 & 0xFFFF0000u);
            uint32_t l0 = pack_bf16x2(f.y - a1, f.x - a0);
            uint32_t l1 = pack_bf16x2(f.w - a3, f.z - a2);
            *(uint2*)(tile_gen + stage + A_HI_OFF + off) = make_uint2(h0, h1);
            *(uint2*)(tile_gen + stage + A_LO_OFF + off) = make_uint2(l0, l1);
        }
        #pragma unroll
        for (int p = 0; p < 8; p++) {
            const uint32_t off = SWZ64(rowOff + (uint32_t)p * 2048);
            float4 f = bufB[p];
            uint32_t h0 = pack_bf16x2(f.y, f.x);
            uint32_t h1 = pack_bf16x2(f.w, f.z);
            float a0 = __uint_as_float(h0 << 16);
            float a1 = __uint_as_float(h0 & 0xFFFF0000u);
            float a2 = __uint_as_float(h1 << 16);
            float a3 = __uint_as_float(h1 & 0xFFFF0000u);
            uint32_t l0 = pack_bf16x2(f.y - a1, f.x - a0);
            uint32_t l1 = pack_bf16x2(f.w - a3, f.z - a2);
            *(uint2*)(tile_gen + stage + B_HI_OFF + off) = make_uint2(h0, h1);
            *(uint2*)(tile_gen + stage + B_LO_OFF + off) = make_uint2(l0, l1);
        }

        if (i + 1 < niter) {
            const int kt = (i + 1) * BKF;
            #pragma unroll
            for (int q = 0; q < 4; q++) bufA[q] = *(const float4*)(aBase + q * rstep + kt);
            #pragma unroll
            for (int p = 0; p < 8; p++) bufB[p] = *(const float4*)(bBase + p * rstep + kt);
        }

        __syncthreads();

        if (tid == 0) {
            FENCE_ASYNC();
            const uint32_t sb = tile_u32 + stage;
            const uint64_t dAh = mk_desc64(sb + A_HI_OFF);
            const uint64_t dAl = mk_desc64(sb + A_LO_OFF);
            const uint64_t dBh = mk_desc64(sb + B_HI_OFF);
            const uint64_t dBl = mk_desc64(sb + B_LO_OFF);
            const uint32_t en = (i != 0);
            // 4 independent chains: D(h, ks) at tmem + h*128 + ks*256
            #pragma unroll
            for (int ks = 0; ks < 2; ks++) {
                const uint64_t o  = 2 * ks;          // 16 bf16 = 32B = 2 units
                const uint32_t d0 = tmem + (uint32_t)ks * 256;        // half 0
                const uint32_t d1 = d0 + 128;                          // half 1
                mma_bf16_ss(d0, dAh + o, dBh + o,       en);
                mma_bf16_ss(d1, dAh + o, dBh + 512 + o, en);
                mma_bf16_ss(d0, dAh + o, dBl + o,       1);
                mma_bf16_ss(d1, dAh + o, dBl + 512 + o, 1);
                mma_bf16_ss(d0, dAl + o, dBh + o,       1);
                mma_bf16_ss(d1, dAl + o, dBh + 512 + o, 1);
            }
            if      (s == 0) TC_COMMIT(mbar_u32);
            else if (s == 1) TC_COMMIT(mbar_u32 + 8);
            else             TC_COMMIT(mbar_u32 + 16);
        }

        s = (s == NSTAGE - 1) ? 0 : s + 1;
    }

    mbar_wait(mbar_u32,      ph0);
    mbar_wait(mbar_u32 + 8,  ph1);
    mbar_wait(mbar_u32 + 16, ph2);
    TC_FENCE_AFTER();

    // epilogue: warp handles half h = wid>>2, rows (wid&3)*32+lane.
    // C[m, h*128 + c] = D(h,0)[c] + D(h,1)[c]
    {
        const int m = blockRow + (wid & 3) * 32 + lane;
        const int h = wid >> 2;
        #pragma unroll
        for (int cb = 0; cb < 128; cb += 32) {
            uint32_t r0[32], r1[32];
            TC_LD_X32(r0, tmem + (uint32_t)h * 128 + cb);
            TC_LD_X32(r1, tmem + 256 + (uint32_t)h * 128 + cb);
            TC_WAIT_LD();
            float* cr = C + (size_t)m * E + h * 128 + cb;
            #pragma unroll
            for (int q = 0; q < 8; q++) {
                float4 v = make_float4(
                    __uint_as_float(r0[q * 4 + 0]) + __uint_as_float(r1[q * 4 + 0]),
                    __uint_as_float(r0[q * 4 + 1]) + __uint_as_float(r1[q * 4 + 1]),
                    __uint_as_float(r0[q * 4 + 2]) + __uint_as_float(r1[q * 4 + 2]),
                    __uint_as_float(r0[q * 4 + 3]) + __uint_as_float(r1[q * 4 + 3]));
                *(float4*)(cr + q * 4) = v;
            }
        }
        TC_FENCE_BEFORE();
    }
    __syncthreads();
    // PDL: this CTA's C stores are done — allow dependent grid to proceed.
    asm volatile("griddepcontrol.launch_dependents;" ::: "memory");
    if (wid == 0) {
        TC_RELINQ();
        TC_DEALLOC(tmem, TMEM_NCOLS);
    }
#else
    // ==================== SIMT fp32 fallback ==================================
    __shared__ float As[BKF][128];
    __shared__ float Bs[BKF][128];

    const int tid = threadIdx.x;
    const int tx  = tid % 16;
    const int ty  = tid / 16;
    const int blockRow = blockIdx.x * BM;

    for (int half = 0; half < 2; half++) {
        const int blockCol = half * 128;
        const float* Ab = A + (size_t)blockRow * D;
        const float* Bb = W + (size_t)blockCol * D;

        float acc[8][8];
        #pragma unroll
        for (int i = 0; i < 8; i++)
            #pragma unroll
            for (int j = 0; j < 8; j++) acc[i][j] = 0.0f;

        const int lr = tid / 8;
        const int lc = tid % 8;

        for (int kt = 0; kt < D; kt += BKF) {
            __syncthreads();
            #pragma unroll
            for (int i = 0; i < 4; i++) {
                const int row = lr + i * 32;
                float4 va = *(const float4*)(Ab + (size_t)row * D + kt + lc * 4);
                As[lc * 4 + 0][row] = va.x;
                As[lc * 4 + 1][row] = va.y;
                As[lc * 4 + 2][row] = va.z;
                As[lc * 4 + 3][row] = va.w;
                float4 vb = *(const float4*)(Bb + (size_t)row * D + kt + lc * 4);
                Bs[lc * 4 + 0][row] = vb.x;
                Bs[lc * 4 + 1][row] = vb.y;
                Bs[lc * 4 + 2][row] = vb.z;
                Bs[lc * 4 + 3][row] = vb.w;
            }
            __syncthreads();

            #pragma unroll
            for (int k = 0; k < BKF; k++) {
                float a[8], b[8];
                *(float4*)&a[0] = *(const float4*)&As[k][ty * 8];
                *(float4*)&a[4] = *(const float4*)&As[k][ty * 8 + 4];
                *(float4*)&b[0] = *(const float4*)&Bs[k][tx * 8];
                *(float4*)&b[4] = *(const float4*)&Bs[k][tx * 8 + 4];
                #pragma unroll
                for (int i = 0; i < 8; i++)
                    #pragma unroll
                    for (int j = 0; j < 8; j++)
                        acc[i][j] = fmaf(a[i], b[j], acc[i][j]);
            }
        }

        #pragma unroll
        for (int i = 0; i < 8; i++) {
            const int row = blockRow + ty * 8 + i;
            float* Cr = C + (size_t)row * E + blockCol + tx * 8;
            *(float4*)(Cr + 0) = make_float4(acc[i][0], acc[i][1], acc[i][2], acc[i][3]);
            *(float4*)(Cr + 4) = make_float4(acc[i][4], acc[i][5], acc[i][6], acc[i][7]);
        }
        __syncthreads();
    }
    asm volatile("griddepcontrol.launch_dependents;" ::: "memory");
#endif
}

// ---------------------------------------------------------------------------
// Router: warp per token; lane owns 8 experts; redux max. Waits on PDL
// grid-dependency before reading C (hardware-ordered, no custom flags).
// ---------------------------------------------------------------------------
__global__ __launch_bounds__(256)
void router_topk_kernel(const float* __restrict__ C,
                        const float* __restrict__ bias,
                        float* __restrict__ wout,
                        float* __restrict__ iout) {
    const int t    = blockIdx.x * 8 + (threadIdx.x >> 5);
    const int lane = threadIdx.x & 31;

    // bias load overlaps the dependency wait (does not depend on C)
    const float4* bp = (const float4*)bias + lane * 2;
    float4 b0 = __ldg(bp), b1 = __ldg(bp + 1);
    float bl[8] = {b0.x, b0.y, b0.z, b0.w, b1.x, b1.y, b1.z, b1.w};

    // PDL: block until the GEMM grid's C writes are visible
    asm volatile("griddepcontrol.wait;" ::: "memory");

    const float4* row = (const float4*)(C + (size_t)t * 256) + lane * 2;
    float4 v0 = row[0], v1 = row[1];
    float sc[8] = {v0.x, v0.y, v0.z, v0.w, v1.x, v1.y, v1.z, v1.w};

    // softmax
    float m = sc[0];
    #pragma unroll
    for (int j = 1; j < 8; j++) m = fmaxf(m, sc[j]);
    m = warp_max_f32(m);

    float ex[8];
    float su = 0.0f;
    #pragma unroll
    for (int j = 0; j < 8; j++) { ex[j] = __expf(sc[j] - m); su += ex[j]; }
    #pragma unroll
    for (int off = 16; off > 0; off >>= 1)
        su += __shfl_xor_sync(0xffffffffu, su, off);
    const float inv = 1.0f / su;

    float prob[8], choice[8];
    #pragma unroll
    for (int j = 0; j < 8; j++) {
        prob[j]   = ex[j] * inv;
        choice[j] = prob[j] + bl[j];
    }

    // cached local argmax (lowest j on ties via strict >)
    float v = choice[0];
    int   li = 0;
    #pragma unroll
    for (int j = 1; j < 8; j++)
        if (choice[j] > v) { v = choice[j]; li = j; }

    #pragma unroll
    for (int k = 0; k < TOP_K; k++) {
        const float g = warp_max_f32(v);
        unsigned mask = __ballot_sync(0xffffffffu, v == g);
        int src = __ffs(mask) - 1;
        if (lane == src) {
            float pw = 0.0f;
            #pragma unroll
            for (int j = 0; j < 8; j++)
                if (j == li) { pw = prob[j]; choice[j] = -INFINITY; }
            wout[(size_t)t * TOP_K + k] = pw * ROUTED_SCALE;
            iout[(size_t)t * TOP_K + k] = (float)(lane * 8 + li);
            v = choice[0]; li = 0;
            #pragma unroll
            for (int j = 1; j < 8; j++)
                if (choice[j] > v) { v = choice[j]; li = j; }
        }
    }
}

// ----------------------------- launch ---------------------------------------
extern "C" void kernel_launch(void* const* d_in, const int* in_sizes, int n_in,
                              void* d_out, int out_size) {
    const float* H    = (const float*)d_in[0];  // [T, D]
    const float* W    = (const float*)d_in[1];  // [E, D]
    const float* bias = (const float*)d_in[2];  // [E]

    const int E = in_sizes[2];                  // 256
    const int D = in_sizes[1] / E;              // 4096
    const int T = in_sizes[0] / D;              // 16384

    float* out  = (float*)d_out;
    float* C    = out;                          // [T, E]
    float* wout = out + (size_t)T * E;          // [T, 8]
    float* iout = wout + (size_t)T * TOP_K;     // [T, 8]

    static int attr_set = 0;
    if (!attr_set) {
        cudaFuncSetAttribute(gemm_kernel,
                             cudaFuncAttributeMaxDynamicSharedMemorySize, DYN_SMEM);
        attr_set = 1;
    }

    gemm_kernel<<<T / BM, 256, DYN_SMEM>>>(H, W, C, D, E);

    // Router with programmatic dependent launch (hardware-ordered overlap).
    cudaLaunchConfig_t cfg = {};
    cfg.gridDim  = dim3((unsigned)(T / 8), 1, 1);
    cfg.blockDim = dim3(256, 1, 1);
    cfg.dynamicSmemBytes = 0;
    cfg.stream = 0;
    cudaLaunchAttribute at[1];
    at[0].id = cudaLaunchAttributeProgrammaticStreamSerialization;
    at[0].val.programmaticStreamSerializationAllowed = 1;
    cfg.attrs = at;
    cfg.numAttrs = 1;
    cudaError_t e = cudaLaunchKernelEx(&cfg, router_topk_kernel, C, bias, wout, iout);
    if (e != cudaSuccess) {
        cudaGetLastError();   // clear; plain serialized launch (identical result)
        router_topk_kernel<<<T / 8, 256>>>(C, bias, wout, iout);
    }
}